// round 16
// baseline (speedup 1.0000x reference)
#include <cuda_runtime.h>
#include <stdint.h>

// ============================================================================
// HeteroscedasticSoftmax: out = mean_{s<100} softmax(logits + eps_s * exp(log_std))
// eps_s reproduces jax.random.normal(split(key(1),100)[s], [8,19,256,256])
// bit-exactly (partitionable threefry2x32; draw = x0^x1; XLA/Giles erfinv).
//
// R15: alu-mix rebalance. Measured alu = 42/draw (SHF20+LOP321+FMNMX) = 59%
// of issue mix -> issue ceiling 0.5/0.59 = 85% (we sit at 82). Convert the
// three r=26 rotations to MUL.LO+MAD.HI pairs on the fma pipe (wrap-add ==
// or; opaque multiplier) -> mix 52:48, ceiling ~92%. Offset slots by
// truncating the common-path Giles poly 9->8 terms (c8 ~ 7e-6 rel typical).
// ============================================================================

#define NSAMP 100
#define NCH   19
#define NB    8
#define HW    65536            // 256*256

// Dynamic smem layout: [0,800) keys, [800, 800+19456) lgsd float2
#define SMEM_KEYS   0
#define SMEM_LGSD   800
#define SMEM_BYTES  (800 + NCH * 128 * 8)

// Opaque constants — loaded from memory so ptxas cannot strength-reduce the
// IMADs back onto the alu pipe.
__device__ uint32_t d_one = 1u;
__device__ uint32_t d_c26 = 1u << 26;

__device__ __forceinline__ uint32_t imad1(uint32_t a, uint32_t one, uint32_t b) {
  uint32_t r;
  asm("mad.lo.u32 %0, %1, %2, %3;" : "=r"(r) : "r"(a), "r"(one), "r"(b));
  return r;
}
__device__ __forceinline__ uint32_t imul_lo(uint32_t a, uint32_t c) {
  uint32_t r;
  asm("mul.lo.u32 %0, %1, %2;" : "=r"(r) : "r"(a), "r"(c));
  return r;
}
__device__ __forceinline__ uint32_t imad_hi(uint32_t a, uint32_t c, uint32_t b) {
  uint32_t r;
  asm("mad.hi.u32 %0, %1, %2, %3;" : "=r"(r) : "r"(a), "r"(c), "r"(b));
  return r;
}

// (bits >> 9) + 0x3F800000 on the fma pipe (IMAD.HI); equals OR (disjoint bits).
__device__ __forceinline__ uint32_t mantissa_to_one_two(uint32_t bits) {
  uint32_t r;
  asm("mad.hi.u32 %0, %1, %2, %3;" : "=r"(r)
      : "r"(bits), "n"(1u << 23), "n"(0x3F800000u));
  return r;
}

__device__ __forceinline__ float ex2_approx(float x) {
  float r; asm("ex2.approx.f32 %0, %1;" : "=f"(r) : "f"(x)); return r;
}
__device__ __forceinline__ float lg2_approx(float x) {
  float r; asm("lg2.approx.f32 %0, %1;" : "=f"(r) : "f"(x)); return r;
}
__device__ __forceinline__ float sqrt_approx(float x) {
  float r; asm("sqrt.approx.f32 %0, %1;" : "=f"(r) : "f"(x)); return r;
}
__device__ __forceinline__ float rcp_approx(float x) {
  float r; asm("rcp.approx.f32 %0, %1;" : "=f"(r) : "f"(x)); return r;
}

// Threefry2x32 (20 rounds). Adds + the three r=26 rotations on the fma pipe
// (IMAD / MUL.LO+MAD.HI with opaque 2^26: lo = x<<26, hi+lo == rotate since
// the halves are bit-disjoint); remaining rotations on SHF (alu).
// Caller pre-injects (x0 = k0, x1 = ctr + k1). Returns x0^x1.
__device__ __forceinline__ uint32_t threefry2x32_x(
    uint32_t x0, uint32_t x1,
    uint32_t j1a, uint32_t j1b, uint32_t j2a, uint32_t j2b,
    uint32_t j3a, uint32_t j3b, uint32_t j4a, uint32_t j4b,
    uint32_t j5a, uint32_t j5b, uint32_t one, uint32_t c26) {
#define TF_ROUND(r) { x0 = imad1(x0, one, x1); x1 = __funnelshift_l(x1, x1, (r)); x1 ^= x0; }
#define TF_ROUND_M() { x0 = imad1(x0, one, x1); uint32_t lo_ = imul_lo(x1, c26); x1 = imad_hi(x1, c26, lo_); x1 ^= x0; }
#define TF_INJ(a, b) { x0 = imad1(x0, one, (a)); x1 = imad1(x1, one, (b)); }
  TF_ROUND(13) TF_ROUND(15) TF_ROUND_M() TF_ROUND(6)
  TF_INJ(j1a, j1b)
  TF_ROUND(17) TF_ROUND(29) TF_ROUND(16) TF_ROUND(24)
  TF_INJ(j2a, j2b)
  TF_ROUND(13) TF_ROUND(15) TF_ROUND_M() TF_ROUND(6)
  TF_INJ(j3a, j3b)
  TF_ROUND(17) TF_ROUND(29) TF_ROUND(16) TF_ROUND(24)
  TF_INJ(j4a, j4b)
  TF_ROUND(13) TF_ROUND(15) TF_ROUND_M() TF_ROUND(6)
  TF_INJ(j5a, j5b)
#undef TF_ROUND
#undef TF_ROUND_M
#undef TF_INJ
  return x0 ^ x1;
}

// Plain version (key derivation only; once per block).
__device__ __forceinline__ uint2 threefry2x32(uint32_t k0, uint32_t k1,
                                              uint32_t x0, uint32_t x1) {
  uint32_t k2 = k0 ^ k1 ^ 0x1BD11BDAu;
  x0 += k0; x1 += k1;
#define TF_ROUND(r) { x0 += x1; x1 = __funnelshift_l(x1, x1, (r)); x1 ^= x0; }
  TF_ROUND(13) TF_ROUND(15) TF_ROUND(26) TF_ROUND(6)
  x0 += k1; x1 += k2 + 1u;
  TF_ROUND(17) TF_ROUND(29) TF_ROUND(16) TF_ROUND(24)
  x0 += k2; x1 += k0 + 2u;
  TF_ROUND(13) TF_ROUND(15) TF_ROUND(26) TF_ROUND(6)
  x0 += k0; x1 += k1 + 3u;
  TF_ROUND(17) TF_ROUND(29) TF_ROUND(16) TF_ROUND(24)
  x0 += k1; x1 += k2 + 4u;
  TF_ROUND(13) TF_ROUND(15) TF_ROUND(26) TF_ROUND(6)
  x0 += k2; x1 += k0 + 5u;
#undef TF_ROUND
  return make_uint2(x0, x1);
}

#define NEG_LN2 (-0.69314718f)
// w = -ln2*lg2(y); branch "w < 5"  <=>  lg2(y) > 5/-ln2
#define LG2_BRANCH (-7.21347520f)

// XLA ErfInv32 (Giles) WITHOUT sqrt2 (folded into sd prescale). Branchless.
// Common path truncated 9->8 terms (c8 contributes ~7e-6 rel on typical
// draws; budget is 1e-3). Rare path: 5-term poly in v = sqrt(-ln2*wl).
__device__ __forceinline__ float erfinv_raw(float x) {
  float y = fmaf(-x, x, 1.0f);          // 1 - x^2  (>= ~1.2e-7, never <= 0)
  float wl = lg2_approx(y);             // lg2(y); w = -ln2 * wl
  // common path (w < 5): ~99.66% of draws — 8-term Giles poly
  float w1 = fmaf(wl, NEG_LN2, -2.5f);  // w - 2.5 fused
  float p1 = 3.43273939e-07f;
  p1 = fmaf(p1, w1, -3.5233877e-06f);
  p1 = fmaf(p1, w1, -4.39150654e-06f);
  p1 = fmaf(p1, w1, 0.00021858087f);
  p1 = fmaf(p1, w1, -0.00125372503f);
  p1 = fmaf(p1, w1, -0.00417768164f);
  p1 = fmaf(p1, w1, 0.246640727f);
  p1 = fmaf(p1, w1, 1.50140941f);
  // rare path (w >= 5): tail |x| > ~0.998; poly in v = sqrt(w)
  float v = sqrt_approx(wl * NEG_LN2);
  float p2 = 0.00573950773f;
  p2 = fmaf(p2, v, -0.076496554f);
  p2 = fmaf(p2, v, 0.387974440f);
  p2 = fmaf(p2, v, 0.119367547f);
  p2 = fmaf(p2, v, 0.583610515f);
  float p = (wl > LG2_BRANCH) ? p1 : p2;   // single FSEL, no BSSY/BSYNC
  return p * x;
}

__device__ __forceinline__ float bits_to_eps_raw(uint32_t bits) {
  float g = __uint_as_float(mantissa_to_one_two(bits));  // [1, 2)
  // u = 2(g-1) + lo == fma(g, 2, lo-2); rn(lo-2) = -3.0 exactly.
  float u = fmaf(g, 2.0f, -3.0f);
  return erfinv_raw(u);              // sqrt2 folded into sd prescale
}

#define LOG2E 1.44269504f
#define SQRT2_LOG2E 2.04009342f       // sqrt(2) * log2(e)

__global__ __launch_bounds__(128, 9)
void hs_main_kernel(const float* __restrict__ in, float* __restrict__ out) {
  extern __shared__ char smem[];
  uint2*  sk   = (uint2*)(smem + SMEM_KEYS);
  float2* lgsd = (float2*)(smem + SMEM_LGSD);   // [c*128 + t]
  int t = threadIdx.x;
  // Derive the 100 sample keys from jax.random.key(1) = (0, 1) in-block.
  if (t < NSAMP) sk[t] = threefry2x32(0u, 1u, 0u, (uint32_t)t);

  const uint32_t one = d_one;
  const uint32_t c26 = d_c26;

  unsigned T = blockIdx.x * 128u + (unsigned)t;   // 0 .. 524287
  unsigned b = T >> 16;
  unsigned hw = T & 0xFFFFu;

  const float* pin = in + (size_t)b * (2 * NCH) * HW + hw;
#pragma unroll
  for (int c = 0; c < NCH; c++) {
    float l = pin[(size_t)c * HW];
    float s = __expf(pin[(size_t)(NCH + c) * HW]);
    lgsd[c * 128 + t] = make_float2(l * LOG2E, s * SQRT2_LOG2E);
  }
  __syncthreads();

  float acc[NCH];
#pragma unroll
  for (int c = 0; c < NCH; c++) acc[c] = 0.0f;

  const uint32_t ctrBase = b * (NCH * HW) + hw;   // flat idx of (b, 0, hw)

#pragma unroll 1
  for (int s = 0; s < NSAMP; s++) {
    const uint2 k = sk[s];
    const uint32_t k0 = k.x, k1 = k.y;
    const uint32_t k2 = k0 ^ k1 ^ 0x1BD11BDAu;
    const uint32_t j1b = k2 + 1u, j2b = k0 + 2u, j3b = k1 + 3u,
                   j4b = k2 + 4u, j5b = k0 + 5u;
    const uint32_t x1base = ctrBase + k1;   // counter lo + initial k1 inject
    float z[NCH];
#pragma unroll
    for (int c = 0; c < NCH; c++) {
      // counter = (0, ctrBase + c*HW); x0 init = 0 + k0.
      uint32_t x1 = imad1(x1base, one, (uint32_t)c << 16);
      uint32_t bits = threefry2x32_x(k0, x1,
                                     k1, j1b, k2, j2b, k0, j3b,
                                     k1, j4b, k2, j5b, one, c26);
      float er = bits_to_eps_raw(bits);
      float2 ls = lgsd[c * 128 + t];
      z[c] = fmaf(er, ls.y, ls.x);       // log2-domain logits+eps*std
    }
    // softmax over channels in log2 domain — tree max
    float m;
    {
      float t0 = fmaxf(z[0], z[1]),  t1 = fmaxf(z[2], z[3]);
      float t2 = fmaxf(z[4], z[5]),  t3 = fmaxf(z[6], z[7]);
      float t4 = fmaxf(z[8], z[9]),  t5 = fmaxf(z[10], z[11]);
      float t6 = fmaxf(z[12], z[13]), t7 = fmaxf(z[14], z[15]);
      float t8 = fmaxf(z[16], z[17]);
      t0 = fmaxf(t0, t1); t2 = fmaxf(t2, t3); t4 = fmaxf(t4, t5);
      t6 = fmaxf(t6, t7); t8 = fmaxf(t8, z[18]);
      t0 = fmaxf(t0, t2); t4 = fmaxf(t4, t6);
      m = fmaxf(fmaxf(t0, t4), t8);
    }
#pragma unroll
    for (int c = 0; c < NCH; c++) z[c] = ex2_approx(z[c] - m);
    // tree sum
    float sum;
    {
      float t0 = z[0] + z[1],  t1 = z[2] + z[3];
      float t2 = z[4] + z[5],  t3 = z[6] + z[7];
      float t4 = z[8] + z[9],  t5 = z[10] + z[11];
      float t6 = z[12] + z[13], t7 = z[14] + z[15];
      float t8 = z[16] + z[17];
      t0 += t1; t2 += t3; t4 += t5; t6 += t7; t8 += z[18];
      t0 += t2; t4 += t6;
      sum = (t0 + t4) + t8;
    }
    float inv = rcp_approx(sum);         // 0.01 folded into the final store
#pragma unroll
    for (int c = 0; c < NCH; c++) acc[c] = fmaf(z[c], inv, acc[c]);
  }

  float* pout = out + (size_t)b * NCH * HW + hw;
#pragma unroll
  for (int c = 0; c < NCH; c++) pout[(size_t)c * HW] = acc[c] * 0.01f;
}

extern "C" void kernel_launch(void* const* d_in, const int* in_sizes, int n_in,
                              void* d_out, int out_size) {
  (void)in_sizes; (void)n_in; (void)out_size;
  const float* in = (const float*)d_in[0];
  float* out = (float*)d_out;

  // Host-side attribute write, idempotent, graph-capture-safe, no static state.
  cudaFuncSetAttribute(hs_main_kernel,
                       cudaFuncAttributeMaxDynamicSharedMemorySize, SMEM_BYTES);

  // 8 batches * 65536 spatial = 524288 threads, one per (b, h, w)
  hs_main_kernel<<<4096, 128, SMEM_BYTES>>>(in, out);
}

// round 17
// speedup vs baseline: 1.0130x; 1.0130x over previous
#include <cuda_runtime.h>
#include <stdint.h>

// ============================================================================
// HeteroscedasticSoftmax: out = mean_{s<100} softmax(logits + eps_s * exp(log_std))
// eps_s reproduces jax.random.normal(split(key(1),100)[s], [8,19,256,256])
// bit-exactly (partitionable threefry2x32; draw = x0^x1; XLA/Giles erfinv).
//
// R16 = R14 structure (best: pure-SHF threefry rotations, IMAD adds, reg cap
// 56, dynamic smem) + common-path Giles poly truncated 8->7 terms (-1 fma
// slot/draw; dropped term <= 2e-4 abs only near the 1% tail region).
// Rotate-via-IMAD experiments (R6, R15) are closed: alu/draw provably did
// not drop either time.
// ============================================================================

#define NSAMP 100
#define NCH   19
#define NB    8
#define HW    65536            // 256*256

// Dynamic smem layout: [0,800) keys, [800, 800+19456) lgsd float2
#define SMEM_KEYS   0
#define SMEM_LGSD   800
#define SMEM_BYTES  (800 + NCH * 128 * 8)

// Opaque 1 — keeps integer adds as IMAD (fma pipe) instead of IADD3 (alu).
__device__ uint32_t d_one = 1u;

__device__ __forceinline__ uint32_t imad1(uint32_t a, uint32_t one, uint32_t b) {
  uint32_t r;
  asm("mad.lo.u32 %0, %1, %2, %3;" : "=r"(r) : "r"(a), "r"(one), "r"(b));
  return r;
}

// (bits >> 9) + 0x3F800000 on the fma pipe (IMAD.HI); equals OR (disjoint bits).
__device__ __forceinline__ uint32_t mantissa_to_one_two(uint32_t bits) {
  uint32_t r;
  asm("mad.hi.u32 %0, %1, %2, %3;" : "=r"(r)
      : "r"(bits), "n"(1u << 23), "n"(0x3F800000u));
  return r;
}

__device__ __forceinline__ float ex2_approx(float x) {
  float r; asm("ex2.approx.f32 %0, %1;" : "=f"(r) : "f"(x)); return r;
}
__device__ __forceinline__ float lg2_approx(float x) {
  float r; asm("lg2.approx.f32 %0, %1;" : "=f"(r) : "f"(x)); return r;
}
__device__ __forceinline__ float sqrt_approx(float x) {
  float r; asm("sqrt.approx.f32 %0, %1;" : "=f"(r) : "f"(x)); return r;
}
__device__ __forceinline__ float rcp_approx(float x) {
  float r; asm("rcp.approx.f32 %0, %1;" : "=f"(r) : "f"(x)); return r;
}

// Threefry2x32 (20 rounds), adds on fma pipe (IMAD), rotations on SHF.
// Caller pre-injects (x0 = k0, x1 = ctr + k1). Returns x0^x1.
__device__ __forceinline__ uint32_t threefry2x32_x(
    uint32_t x0, uint32_t x1,
    uint32_t j1a, uint32_t j1b, uint32_t j2a, uint32_t j2b,
    uint32_t j3a, uint32_t j3b, uint32_t j4a, uint32_t j4b,
    uint32_t j5a, uint32_t j5b, uint32_t one) {
#define TF_ROUND(r) { x0 = imad1(x0, one, x1); x1 = __funnelshift_l(x1, x1, (r)); x1 ^= x0; }
#define TF_INJ(a, b) { x0 = imad1(x0, one, (a)); x1 = imad1(x1, one, (b)); }
  TF_ROUND(13) TF_ROUND(15) TF_ROUND(26) TF_ROUND(6)
  TF_INJ(j1a, j1b)
  TF_ROUND(17) TF_ROUND(29) TF_ROUND(16) TF_ROUND(24)
  TF_INJ(j2a, j2b)
  TF_ROUND(13) TF_ROUND(15) TF_ROUND(26) TF_ROUND(6)
  TF_INJ(j3a, j3b)
  TF_ROUND(17) TF_ROUND(29) TF_ROUND(16) TF_ROUND(24)
  TF_INJ(j4a, j4b)
  TF_ROUND(13) TF_ROUND(15) TF_ROUND(26) TF_ROUND(6)
  TF_INJ(j5a, j5b)
#undef TF_ROUND
#undef TF_INJ
  return x0 ^ x1;
}

// Plain version (key derivation only; once per block).
__device__ __forceinline__ uint2 threefry2x32(uint32_t k0, uint32_t k1,
                                              uint32_t x0, uint32_t x1) {
  uint32_t k2 = k0 ^ k1 ^ 0x1BD11BDAu;
  x0 += k0; x1 += k1;
#define TF_ROUND(r) { x0 += x1; x1 = __funnelshift_l(x1, x1, (r)); x1 ^= x0; }
  TF_ROUND(13) TF_ROUND(15) TF_ROUND(26) TF_ROUND(6)
  x0 += k1; x1 += k2 + 1u;
  TF_ROUND(17) TF_ROUND(29) TF_ROUND(16) TF_ROUND(24)
  x0 += k2; x1 += k0 + 2u;
  TF_ROUND(13) TF_ROUND(15) TF_ROUND(26) TF_ROUND(6)
  x0 += k0; x1 += k1 + 3u;
  TF_ROUND(17) TF_ROUND(29) TF_ROUND(16) TF_ROUND(24)
  x0 += k1; x1 += k2 + 4u;
  TF_ROUND(13) TF_ROUND(15) TF_ROUND(26) TF_ROUND(6)
  x0 += k2; x1 += k0 + 5u;
#undef TF_ROUND
  return make_uint2(x0, x1);
}

#define NEG_LN2 (-0.69314718f)
// w = -ln2*lg2(y); branch "w < 5"  <=>  lg2(y) > 5/-ln2
#define LG2_BRANCH (-7.21347520f)

// XLA ErfInv32 (Giles) WITHOUT sqrt2 (folded into sd prescale). Branchless.
// Common path truncated to 7 terms (dropped c7,c8: <=2.5e-4 abs near |u|~1,
// ~1e-6 typical; output budget 1e-3). Rare path: 5-term poly in v.
__device__ __forceinline__ float erfinv_raw(float x) {
  float y = fmaf(-x, x, 1.0f);          // 1 - x^2  (>= ~1.2e-7, never <= 0)
  float wl = lg2_approx(y);             // lg2(y); w = -ln2 * wl
  // common path (w < 5): ~99.66% of draws — 7-term Giles poly
  float w1 = fmaf(wl, NEG_LN2, -2.5f);  // w - 2.5 fused
  float p1 = -3.5233877e-06f;
  p1 = fmaf(p1, w1, -4.39150654e-06f);
  p1 = fmaf(p1, w1, 0.00021858087f);
  p1 = fmaf(p1, w1, -0.00125372503f);
  p1 = fmaf(p1, w1, -0.00417768164f);
  p1 = fmaf(p1, w1, 0.246640727f);
  p1 = fmaf(p1, w1, 1.50140941f);
  // rare path (w >= 5): tail |x| > ~0.998; poly in v = sqrt(w) (no -3 FADD)
  float v = sqrt_approx(wl * NEG_LN2);
  float p2 = 0.00573950773f;
  p2 = fmaf(p2, v, -0.076496554f);
  p2 = fmaf(p2, v, 0.387974440f);
  p2 = fmaf(p2, v, 0.119367547f);
  p2 = fmaf(p2, v, 0.583610515f);
  float p = (wl > LG2_BRANCH) ? p1 : p2;   // single FSEL, no BSSY/BSYNC
  return p * x;
}

__device__ __forceinline__ float bits_to_eps_raw(uint32_t bits) {
  float g = __uint_as_float(mantissa_to_one_two(bits));  // [1, 2)
  // u = 2(g-1) + lo == fma(g, 2, lo-2); rn(lo-2) = -3.0 exactly.
  float u = fmaf(g, 2.0f, -3.0f);
  return erfinv_raw(u);              // sqrt2 folded into sd prescale
}

#define LOG2E 1.44269504f
#define SQRT2_LOG2E 2.04009342f       // sqrt(2) * log2(e)

__global__ __launch_bounds__(128, 9)
void hs_main_kernel(const float* __restrict__ in, float* __restrict__ out) {
  extern __shared__ char smem[];
  uint2*  sk   = (uint2*)(smem + SMEM_KEYS);
  float2* lgsd = (float2*)(smem + SMEM_LGSD);   // [c*128 + t]
  int t = threadIdx.x;
  // Derive the 100 sample keys from jax.random.key(1) = (0, 1) in-block.
  if (t < NSAMP) sk[t] = threefry2x32(0u, 1u, 0u, (uint32_t)t);

  const uint32_t one = d_one;

  unsigned T = blockIdx.x * 128u + (unsigned)t;   // 0 .. 524287
  unsigned b = T >> 16;
  unsigned hw = T & 0xFFFFu;

  const float* pin = in + (size_t)b * (2 * NCH) * HW + hw;
#pragma unroll
  for (int c = 0; c < NCH; c++) {
    float l = pin[(size_t)c * HW];
    float s = __expf(pin[(size_t)(NCH + c) * HW]);
    lgsd[c * 128 + t] = make_float2(l * LOG2E, s * SQRT2_LOG2E);
  }
  __syncthreads();

  float acc[NCH];
#pragma unroll
  for (int c = 0; c < NCH; c++) acc[c] = 0.0f;

  const uint32_t ctrBase = b * (NCH * HW) + hw;   // flat idx of (b, 0, hw)

#pragma unroll 1
  for (int s = 0; s < NSAMP; s++) {
    const uint2 k = sk[s];
    const uint32_t k0 = k.x, k1 = k.y;
    const uint32_t k2 = k0 ^ k1 ^ 0x1BD11BDAu;
    const uint32_t j1b = k2 + 1u, j2b = k0 + 2u, j3b = k1 + 3u,
                   j4b = k2 + 4u, j5b = k0 + 5u;
    const uint32_t x1base = ctrBase + k1;   // counter lo + initial k1 inject
    float z[NCH];
#pragma unroll
    for (int c = 0; c < NCH; c++) {
      // counter = (0, ctrBase + c*HW); x0 init = 0 + k0.
      uint32_t x1 = imad1(x1base, one, (uint32_t)c << 16);
      uint32_t bits = threefry2x32_x(k0, x1,
                                     k1, j1b, k2, j2b, k0, j3b,
                                     k1, j4b, k2, j5b, one);
      float er = bits_to_eps_raw(bits);
      float2 ls = lgsd[c * 128 + t];
      z[c] = fmaf(er, ls.y, ls.x);       // log2-domain logits+eps*std
    }
    // softmax over channels in log2 domain — tree max
    float m;
    {
      float t0 = fmaxf(z[0], z[1]),  t1 = fmaxf(z[2], z[3]);
      float t2 = fmaxf(z[4], z[5]),  t3 = fmaxf(z[6], z[7]);
      float t4 = fmaxf(z[8], z[9]),  t5 = fmaxf(z[10], z[11]);
      float t6 = fmaxf(z[12], z[13]), t7 = fmaxf(z[14], z[15]);
      float t8 = fmaxf(z[16], z[17]);
      t0 = fmaxf(t0, t1); t2 = fmaxf(t2, t3); t4 = fmaxf(t4, t5);
      t6 = fmaxf(t6, t7); t8 = fmaxf(t8, z[18]);
      t0 = fmaxf(t0, t2); t4 = fmaxf(t4, t6);
      m = fmaxf(fmaxf(t0, t4), t8);
    }
#pragma unroll
    for (int c = 0; c < NCH; c++) z[c] = ex2_approx(z[c] - m);
    // tree sum
    float sum;
    {
      float t0 = z[0] + z[1],  t1 = z[2] + z[3];
      float t2 = z[4] + z[5],  t3 = z[6] + z[7];
      float t4 = z[8] + z[9],  t5 = z[10] + z[11];
      float t6 = z[12] + z[13], t7 = z[14] + z[15];
      float t8 = z[16] + z[17];
      t0 += t1; t2 += t3; t4 += t5; t6 += t7; t8 += z[18];
      t0 += t2; t4 += t6;
      sum = (t0 + t4) + t8;
    }
    float inv = rcp_approx(sum);         // 0.01 folded into the final store
#pragma unroll
    for (int c = 0; c < NCH; c++) acc[c] = fmaf(z[c], inv, acc[c]);
  }

  float* pout = out + (size_t)b * NCH * HW + hw;
#pragma unroll
  for (int c = 0; c < NCH; c++) pout[(size_t)c * HW] = acc[c] * 0.01f;
}

extern "C" void kernel_launch(void* const* d_in, const int* in_sizes, int n_in,
                              void* d_out, int out_size) {
  (void)in_sizes; (void)n_in; (void)out_size;
  const float* in = (const float*)d_in[0];
  float* out = (float*)d_out;

  // Host-side attribute write, idempotent, graph-capture-safe, no static state.
  cudaFuncSetAttribute(hs_main_kernel,
                       cudaFuncAttributeMaxDynamicSharedMemorySize, SMEM_BYTES);

  // 8 batches * 65536 spatial = 524288 threads, one per (b, h, w)
  hs_main_kernel<<<4096, 128, SMEM_BYTES>>>(in, out);
}